// round 4
// baseline (speedup 1.0000x reference)
#include <cuda_runtime.h>
#include <math.h>
#include <stdint.h>

#define NB 256
#define S  4096
#define FO 8
#define NM 64
#define FM 6
#define EPSF 1e-5f

#define PC    8                 // CTAs per cluster (per proc instance)
#define NCLU  16                // clusters (persistent)
#define GRID  (NCLU * PC)       // 128 CTAs, all resident
#define PT    512               // threads per CTA
#define CHUNK 8192              // float4 per proc CTA chunk (128 KB)
#define OCH   8192              // float4 per opes instance (128 KB)
#define PROC_IT (NB / NCLU)     // 16 proc instances per cluster
#define OPES_IT (NB / GRID)     // 2 opes instances per CTA

__device__ __forceinline__ float warp_sum(float v) {
#pragma unroll
    for (int o = 16; o > 0; o >>= 1) v += __shfl_down_sync(0xffffffffu, v, o);
    return v;
}

__device__ __forceinline__ uint32_t smem_u32(const void* p) {
    return (uint32_t)__cvta_generic_to_shared((void*)p);
}

__device__ __forceinline__ void dsmem_st_f32(uint32_t laddr, uint32_t rank, float v) {
    uint32_t r;
    asm volatile("mapa.shared::cluster.u32 %0, %1, %2;" : "=r"(r) : "r"(laddr), "r"(rank));
    asm volatile("st.shared::cluster.f32 [%0], %1;" :: "r"(r), "f"(v));
}

__device__ __forceinline__ void cluster_sync_() {
    asm volatile("barrier.cluster.arrive.aligned;" ::: "memory");
    asm volatile("barrier.cluster.wait.aligned;" ::: "memory");
}

__global__ void __cluster_dims__(PC, 1, 1) __launch_bounds__(PT, 1)
fused_k(const float4* __restrict__ pt, float4* __restrict__ out_proc,
        const float* __restrict__ opes, const float* __restrict__ mas,
        const int* __restrict__ nums,
        float* __restrict__ out_opes, float* __restrict__ out_mas) {
    extern __shared__ char dyn[];
    float4* data = (float4*)dyn;                      // 8192 float4 = 128 KB

    __shared__ float stats[2][PC][4];                 // double-buffered cluster partials
    __shared__ float red[3][16];
    __shared__ float bc[3];

    const int rank = blockIdx.x & (PC - 1);
    const int clu  = blockIdx.x >> 3;

    // =================== Phase A: proc_time (cluster single-pass) ===================
    for (int it = 0; it < PROC_IT; it++) {
        const int b = clu + it * NCLU;
        const size_t base = (size_t)b * (S * NM / 4) + (size_t)rank * CHUNK;
        const float4* src = pt + base;
        float4*       dst = out_proc + base;

        float s = 0.f, ss = 0.f, c = 0.f;
#pragma unroll 8
        for (int i = threadIdx.x; i < CHUNK; i += PT) {
            float4 v = __ldcs(src + i);
            data[i] = v;
            s  += (v.x + v.y) + (v.z + v.w);
            ss += (v.x * v.x + v.y * v.y) + (v.z * v.z + v.w * v.w);
            c  += (float)((v.x != 0.f) + (v.y != 0.f) + (v.z != 0.f) + (v.w != 0.f));
        }

        int lane = threadIdx.x & 31, w = threadIdx.x >> 5;
        s = warp_sum(s); ss = warp_sum(ss); c = warp_sum(c);
        if (lane == 0) { red[0][w] = s; red[1][w] = ss; red[2][w] = c; }
        __syncthreads();
        if (threadIdx.x == 0) {
            float a = 0.f, q = 0.f, cc = 0.f;
#pragma unroll
            for (int i = 0; i < 16; i++) { a += red[0][i]; q += red[1][i]; cc += red[2][i]; }
            bc[0] = a; bc[1] = q; bc[2] = cc;
        }
        __syncthreads();

        const int par = it & 1;
        if (threadIdx.x < PC) {
            uint32_t a0 = smem_u32(&stats[par][rank][0]);
            dsmem_st_f32(a0 + 0, threadIdx.x, bc[0]);
            dsmem_st_f32(a0 + 4, threadIdx.x, bc[1]);
            dsmem_st_f32(a0 + 8, threadIdx.x, bc[2]);
        }
        cluster_sync_();

        float St = 0.f, SSt = 0.f, Ct = 0.f;
#pragma unroll
        for (int r2 = 0; r2 < PC; r2++) {
            St += stats[par][r2][0]; SSt += stats[par][r2][1]; Ct += stats[par][r2][2];
        }
        float m   = St / Ct;
        float var = (SSt - St * St / Ct) / (Ct - 1.f);
        float rr  = 1.f / (sqrtf(var) + EPSF);

#pragma unroll 8
        for (int i = threadIdx.x; i < CHUNK; i += PT) {
            float4 v = data[i];      // per-thread-private indices: no cross-thread hazard
            float4 o;
            o.x = (v.x != 0.f) ? (v.x - m) * rr : 0.f;
            o.y = (v.y != 0.f) ? (v.y - m) * rr : 0.f;
            o.z = (v.z != 0.f) ? (v.z - m) * rr : 0.f;
            o.w = (v.w != 0.f) ? (v.w - m) * rr : 0.f;
            __stcs(dst + i, o);
        }
        // next iteration's cluster_sync_ orders smem reuse
    }

    __syncthreads();

    // =================== Phase B: opes (ragged) + mas, per-CTA independent ===================
    __shared__ float4 smas4[NM * FM / 4];
    __shared__ float4 shs[16][2], shq[16][2];
    __shared__ float  M[FO], R[FO], mM[FM], mR[FM];

    for (int j = 0; j < OPES_IT; j++) {
        const int b = blockIdx.x * OPES_IT + j;
        const int n = nums[b];
        const float4* src = (const float4*)(opes + (size_t)b * S * FO);

        // stride PT=512 even -> float4-index parity fixed per thread:
        // even tid => features 0-3, odd tid => features 4-7.
        float4 s4 = make_float4(0.f, 0.f, 0.f, 0.f);
        float4 q4 = make_float4(0.f, 0.f, 0.f, 0.f);
#pragma unroll 8
        for (int i = threadIdx.x; i < OCH; i += PT) {
            float4 v = __ldcs(src + i);
            data[i] = v;
            if ((i >> 1) < n) {
                s4.x += v.x; s4.y += v.y; s4.z += v.z; s4.w += v.w;
                q4.x += v.x * v.x; q4.y += v.y * v.y; q4.z += v.z * v.z; q4.w += v.w * v.w;
            }
        }
        if (threadIdx.x < NM * FM / 4) {
            const float4* msrc = (const float4*)(mas + (size_t)b * NM * FM);
            smas4[threadIdx.x] = msrc[threadIdx.x];
        }

#pragma unroll
        for (int off = 2; off < 32; off <<= 1) {
            s4.x += __shfl_xor_sync(0xffffffffu, s4.x, off);
            s4.y += __shfl_xor_sync(0xffffffffu, s4.y, off);
            s4.z += __shfl_xor_sync(0xffffffffu, s4.z, off);
            s4.w += __shfl_xor_sync(0xffffffffu, s4.w, off);
            q4.x += __shfl_xor_sync(0xffffffffu, q4.x, off);
            q4.y += __shfl_xor_sync(0xffffffffu, q4.y, off);
            q4.z += __shfl_xor_sync(0xffffffffu, q4.z, off);
            q4.w += __shfl_xor_sync(0xffffffffu, q4.w, off);
        }
        int lane = threadIdx.x & 31, w = threadIdx.x >> 5;
        if (lane < 2) { shs[w][lane] = s4; shq[w][lane] = q4; }
        __syncthreads();

        if (threadIdx.x < 32) {
            int p = threadIdx.x & 1, ww = threadIdx.x >> 1;
            float4 a = shs[ww][p], q = shq[ww][p];
#pragma unroll
            for (int off = 2; off < 32; off <<= 1) {
                a.x += __shfl_xor_sync(0xffffffffu, a.x, off);
                a.y += __shfl_xor_sync(0xffffffffu, a.y, off);
                a.z += __shfl_xor_sync(0xffffffffu, a.z, off);
                a.w += __shfl_xor_sync(0xffffffffu, a.w, off);
                q.x += __shfl_xor_sync(0xffffffffu, q.x, off);
                q.y += __shfl_xor_sync(0xffffffffu, q.y, off);
                q.z += __shfl_xor_sync(0xffffffffu, q.z, off);
                q.w += __shfl_xor_sync(0xffffffffu, q.w, off);
            }
            if (threadIdx.x < 2) {
                float fn = (float)n;
                int f0 = p * 4;
                float* sa = &a.x; float* qa = &q.x;
#pragma unroll
                for (int k = 0; k < 4; k++) {
                    float mean = sa[k] / fn;
                    float var  = (qa[k] - sa[k] * sa[k] / fn) / (fn - 1.f);
                    M[f0 + k] = mean;
                    R[f0 + k] = 1.f / (sqrtf(var) + EPSF);
                }
            }
        }
        if (threadIdx.x >= 64 && threadIdx.x < 64 + FM) {
            int f = threadIdx.x - 64;
            const float* sm = (const float*)smas4;
            float ts = 0.f, tq = 0.f;
#pragma unroll
            for (int r2 = 0; r2 < NM; r2++) { float x = sm[r2 * FM + f]; ts += x; tq += x * x; }
            float fm   = (float)NM;
            float mean = ts / fm;
            float var  = (tq - ts * ts / fm) / (fm - 1.f);
            mM[f] = mean;
            mR[f] = 1.f / (sqrtf(var) + EPSF);
        }
        __syncthreads();

        float4* dsto = ((float4*)out_opes) + (size_t)b * OCH;
#pragma unroll 8
        for (int i = threadIdx.x; i < OCH; i += PT) {
            float4 v = data[i];
            int g = (i & 1) * 4;
            float4 o;
            o.x = (v.x - M[g + 0]) * R[g + 0];
            o.y = (v.y - M[g + 1]) * R[g + 1];
            o.z = (v.z - M[g + 2]) * R[g + 2];
            o.w = (v.w - M[g + 3]) * R[g + 3];
            __stcs(dsto + i, o);
        }
        if (threadIdx.x < NM * FM) {
            int f = threadIdx.x % FM;
            float x = ((const float*)smas4)[threadIdx.x];
            __stcs(out_mas + (size_t)b * NM * FM + threadIdx.x, (x - mM[f]) * mR[f]);
        }
        __syncthreads();   // protect smas4 / M / R / shs before next iteration overwrites
    }
}

extern "C" void kernel_launch(void* const* d_in, const int* in_sizes, int n_in,
                              void* d_out, int out_size) {
    const float* raw_opes = (const float*)d_in[0];
    const float* raw_mas  = (const float*)d_in[1];
    const float* proc     = (const float*)d_in[2];
    const int*   nums     = (const int*)d_in[3];

    float* out_opes = (float*)d_out;
    float* out_mas  = out_opes + (size_t)NB * S * FO;
    float* out_proc = out_mas  + (size_t)NB * NM * FM;

    cudaFuncSetAttribute(fused_k, cudaFuncAttributeMaxDynamicSharedMemorySize, CHUNK * 16);

    fused_k<<<GRID, PT, CHUNK * 16>>>((const float4*)proc, (float4*)out_proc,
                                      raw_opes, raw_mas, nums, out_opes, out_mas);
}

// round 5
// speedup vs baseline: 1.0340x; 1.0340x over previous
#include <cuda_runtime.h>
#include <math.h>
#include <stdint.h>

#define NB 256
#define S  4096
#define FO 8
#define NM 64
#define FM 6
#define EPSF 1e-5f

#define PC    8                 // CTAs per cluster (per proc instance)
#define NCLU  16                // clusters
#define GRID  (NCLU * PC)       // 128 CTAs, all resident, safe die packing
#define PT    512               // threads per CTA
#define CHUNK 8192              // float4 per proc CTA chunk (128 KB)
#define SUB   4096              // float4 per sub-buffer (64 KB)
#define SUBB  (SUB * 16)        // bytes per sub-buffer
#define PROC_IT (NB / NCLU)     // 16
#define OPES_IT (NB / GRID)     // 2

__device__ __forceinline__ float warp_sum(float v) {
#pragma unroll
    for (int o = 16; o > 0; o >>= 1) v += __shfl_down_sync(0xffffffffu, v, o);
    return v;
}

__device__ __forceinline__ uint32_t smem_u32(const void* p) {
    return (uint32_t)__cvta_generic_to_shared((void*)p);
}

__device__ __forceinline__ void mbar_init(uint32_t mbar, uint32_t count) {
    asm volatile("mbarrier.init.shared.b64 [%0], %1;" :: "r"(mbar), "r"(count) : "memory");
}

__device__ __forceinline__ void mbar_expect_tx(uint32_t mbar, uint32_t bytes) {
    asm volatile("mbarrier.arrive.expect_tx.shared.b64 _, [%0], %1;"
                 :: "r"(mbar), "r"(bytes) : "memory");
}

__device__ __forceinline__ void mbar_wait(uint32_t mbar, uint32_t parity) {
    asm volatile(
        "{\n\t"
        ".reg .pred P;\n\t"
        "W_%=:\n\t"
        "mbarrier.try_wait.parity.acquire.cta.shared::cta.b64 P, [%0], %1, 0x989680;\n\t"
        "@P bra.uni D_%=;\n\t"
        "bra.uni W_%=;\n\t"
        "D_%=:\n\t"
        "}"
        :: "r"(mbar), "r"(parity) : "memory");
}

__device__ __forceinline__ void bulk_g2s(uint32_t dst, const void* src, uint32_t bytes, uint32_t mbar) {
    asm volatile(
        "cp.async.bulk.shared::cluster.global.mbarrier::complete_tx::bytes [%0], [%1], %2, [%3];"
        :: "r"(dst), "l"(src), "r"(bytes), "r"(mbar) : "memory");
}

__device__ __forceinline__ void dsmem_st_f32(uint32_t laddr, uint32_t rank, float v) {
    uint32_t r;
    asm volatile("mapa.shared::cluster.u32 %0, %1, %2;" : "=r"(r) : "r"(laddr), "r"(rank));
    asm volatile("st.shared::cluster.f32 [%0], %1;" :: "r"(r), "f"(v));
}

__device__ __forceinline__ void cluster_sync_() {
    asm volatile("barrier.cluster.arrive.aligned;" ::: "memory");
    asm volatile("barrier.cluster.wait.aligned;" ::: "memory");
}

__global__ void __cluster_dims__(PC, 1, 1) __launch_bounds__(PT, 1)
fused_k(const float4* __restrict__ pt, float4* __restrict__ out_proc,
        const float* __restrict__ opes, const float* __restrict__ mas,
        const int* __restrict__ nums,
        float* __restrict__ out_opes, float* __restrict__ out_mas) {
    extern __shared__ char dyn[];
    float4* buf = (float4*)dyn;                   // 8192 float4 = 128 KB (2 subs)

    __shared__ uint64_t s_mbar[2];
    __shared__ float stats[2][PC][4];
    __shared__ float red[3][16];
    __shared__ float bc[3];

    const int rank = blockIdx.x & (PC - 1);
    const int clu  = blockIdx.x >> 3;
    const uint32_t mb0  = smem_u32(&s_mbar[0]);
    const uint32_t mb1  = smem_u32(&s_mbar[1]);
    const uint32_t sbuf0 = smem_u32(&buf[0]);
    const uint32_t sbuf1 = smem_u32(&buf[SUB]);
    int ph0 = 0, ph1 = 0;

    if (threadIdx.x == 0) { mbar_init(mb0, 1); mbar_init(mb1, 1); }
    __syncthreads();

    // prologue: prefetch chunk of first proc instance
    if (threadIdx.x == 0) {
        const float4* src = pt + (size_t)clu * (S * NM / 4) + (size_t)rank * CHUNK;
        mbar_expect_tx(mb0, SUBB); bulk_g2s(sbuf0, src,        SUBB, mb0);
        mbar_expect_tx(mb1, SUBB); bulk_g2s(sbuf1, src + SUB,  SUBB, mb1);
    }

    // =================== Phase A: proc_time ===================
    for (int it = 0; it < PROC_IT; it++) {
        const int b = clu + it * NCLU;
        const size_t base = (size_t)b * (S * NM / 4) + (size_t)rank * CHUNK;
        const int has_next = (it + 1 < PROC_IT);
        const float4* nsrc = pt + base + (size_t)NCLU * (S * NM / 4);

        mbar_wait(mb0, ph0); ph0 ^= 1;
        mbar_wait(mb1, ph1); ph1 ^= 1;

        // stats from SMEM
        float s = 0.f, ss = 0.f, c = 0.f;
#pragma unroll 4
        for (int i = threadIdx.x; i < CHUNK; i += PT) {
            float4 v = buf[i];
            s  += (v.x + v.y) + (v.z + v.w);
            ss += (v.x * v.x + v.y * v.y) + (v.z * v.z + v.w * v.w);
            c  += (float)((v.x != 0.f) + (v.y != 0.f) + (v.z != 0.f) + (v.w != 0.f));
        }
        int lane = threadIdx.x & 31, w = threadIdx.x >> 5;
        s = warp_sum(s); ss = warp_sum(ss); c = warp_sum(c);
        if (lane == 0) { red[0][w] = s; red[1][w] = ss; red[2][w] = c; }
        __syncthreads();
        if (threadIdx.x == 0) {
            float a = 0.f, q = 0.f, cc = 0.f;
#pragma unroll
            for (int i = 0; i < 16; i++) { a += red[0][i]; q += red[1][i]; cc += red[2][i]; }
            bc[0] = a; bc[1] = q; bc[2] = cc;
        }
        __syncthreads();

        const int par = it & 1;
        if (threadIdx.x < PC) {
            uint32_t a0 = smem_u32(&stats[par][rank][0]);
            dsmem_st_f32(a0 + 0, threadIdx.x, bc[0]);
            dsmem_st_f32(a0 + 4, threadIdx.x, bc[1]);
            dsmem_st_f32(a0 + 8, threadIdx.x, bc[2]);
        }
        cluster_sync_();

        float St = 0.f, SSt = 0.f, Ct = 0.f;
#pragma unroll
        for (int r2 = 0; r2 < PC; r2++) {
            St += stats[par][r2][0]; SSt += stats[par][r2][1]; Ct += stats[par][r2][2];
        }
        float m   = St / Ct;
        float var = (SSt - St * St / Ct) / (Ct - 1.f);
        float rr  = 1.f / (sqrtf(var) + EPSF);

        float4* dst = out_proc + base;

        // normalize sub0, then immediately refill sub0 with next chunk
#pragma unroll 4
        for (int i = threadIdx.x; i < SUB; i += PT) {
            float4 v = buf[i];
            float4 o;
            o.x = (v.x != 0.f) ? (v.x - m) * rr : 0.f;
            o.y = (v.y != 0.f) ? (v.y - m) * rr : 0.f;
            o.z = (v.z != 0.f) ? (v.z - m) * rr : 0.f;
            o.w = (v.w != 0.f) ? (v.w - m) * rr : 0.f;
            __stcs(dst + i, o);
        }
        __syncthreads();
        if (has_next && threadIdx.x == 0) {
            mbar_expect_tx(mb0, SUBB); bulk_g2s(sbuf0, nsrc, SUBB, mb0);
        }

#pragma unroll 4
        for (int i = SUB + (int)threadIdx.x; i < CHUNK; i += PT) {
            float4 v = buf[i];
            float4 o;
            o.x = (v.x != 0.f) ? (v.x - m) * rr : 0.f;
            o.y = (v.y != 0.f) ? (v.y - m) * rr : 0.f;
            o.z = (v.z != 0.f) ? (v.z - m) * rr : 0.f;
            o.w = (v.w != 0.f) ? (v.w - m) * rr : 0.f;
            __stcs(dst + i, o);
        }
        __syncthreads();
        if (has_next && threadIdx.x == 0) {
            mbar_expect_tx(mb1, SUBB); bulk_g2s(sbuf1, nsrc + SUB, SUBB, mb1);
        }
    }

    // =================== Phase B: opes (ragged) + mas ===================
    __shared__ float4 smas4[NM * FM / 4];
    __shared__ float4 shs[16][2], shq[16][2];
    __shared__ float  M[FO], R[FO], mM[FM], mR[FM];

    // prefetch first opes instance (smem free: last proc iter ended with __syncthreads)
    if (threadIdx.x == 0) {
        const float4* src = (const float4*)(opes + (size_t)(blockIdx.x * OPES_IT) * S * FO);
        mbar_expect_tx(mb0, SUBB); bulk_g2s(sbuf0, src,       SUBB, mb0);
        mbar_expect_tx(mb1, SUBB); bulk_g2s(sbuf1, src + SUB, SUBB, mb1);
    }

    for (int j = 0; j < OPES_IT; j++) {
        const int b = blockIdx.x * OPES_IT + j;
        const int n = nums[b];

        mbar_wait(mb0, ph0); ph0 ^= 1;
        mbar_wait(mb1, ph1); ph1 ^= 1;

        // mas -> smem (tiny, direct LDG)
        if (threadIdx.x < NM * FM / 4) {
            const float4* msrc = (const float4*)(mas + (size_t)b * NM * FM);
            smas4[threadIdx.x] = msrc[threadIdx.x];
        }

        // masked stats; stride PT=512 even -> float4-index parity fixed per thread
        float4 s4 = make_float4(0.f, 0.f, 0.f, 0.f);
        float4 q4 = make_float4(0.f, 0.f, 0.f, 0.f);
#pragma unroll 4
        for (int i = threadIdx.x; i < CHUNK; i += PT) {
            float4 v = buf[i];
            if ((i >> 1) < n) {
                s4.x += v.x; s4.y += v.y; s4.z += v.z; s4.w += v.w;
                q4.x += v.x * v.x; q4.y += v.y * v.y; q4.z += v.z * v.z; q4.w += v.w * v.w;
            }
        }
#pragma unroll
        for (int off = 2; off < 32; off <<= 1) {
            s4.x += __shfl_xor_sync(0xffffffffu, s4.x, off);
            s4.y += __shfl_xor_sync(0xffffffffu, s4.y, off);
            s4.z += __shfl_xor_sync(0xffffffffu, s4.z, off);
            s4.w += __shfl_xor_sync(0xffffffffu, s4.w, off);
            q4.x += __shfl_xor_sync(0xffffffffu, q4.x, off);
            q4.y += __shfl_xor_sync(0xffffffffu, q4.y, off);
            q4.z += __shfl_xor_sync(0xffffffffu, q4.z, off);
            q4.w += __shfl_xor_sync(0xffffffffu, q4.w, off);
        }
        int lane = threadIdx.x & 31, w = threadIdx.x >> 5;
        if (lane < 2) { shs[w][lane] = s4; shq[w][lane] = q4; }
        __syncthreads();

        if (threadIdx.x < 32) {
            int p = threadIdx.x & 1, ww = threadIdx.x >> 1;
            float4 a = shs[ww][p], q = shq[ww][p];
#pragma unroll
            for (int off = 2; off < 32; off <<= 1) {
                a.x += __shfl_xor_sync(0xffffffffu, a.x, off);
                a.y += __shfl_xor_sync(0xffffffffu, a.y, off);
                a.z += __shfl_xor_sync(0xffffffffu, a.z, off);
                a.w += __shfl_xor_sync(0xffffffffu, a.w, off);
                q.x += __shfl_xor_sync(0xffffffffu, q.x, off);
                q.y += __shfl_xor_sync(0xffffffffu, q.y, off);
                q.z += __shfl_xor_sync(0xffffffffu, q.z, off);
                q.w += __shfl_xor_sync(0xffffffffu, q.w, off);
            }
            if (threadIdx.x < 2) {
                float fn = (float)n;
                int f0 = p * 4;
                float* sa = &a.x; float* qa = &q.x;
#pragma unroll
                for (int k = 0; k < 4; k++) {
                    float mean = sa[k] / fn;
                    float var  = (qa[k] - sa[k] * sa[k] / fn) / (fn - 1.f);
                    M[f0 + k] = mean;
                    R[f0 + k] = 1.f / (sqrtf(var) + EPSF);
                }
            }
        }
        if (threadIdx.x >= 64 && threadIdx.x < 64 + FM) {
            int f = threadIdx.x - 64;
            const float* sm = (const float*)smas4;
            float ts = 0.f, tq = 0.f;
#pragma unroll
            for (int r2 = 0; r2 < NM; r2++) { float x = sm[r2 * FM + f]; ts += x; tq += x * x; }
            float fm   = (float)NM;
            float mean = ts / fm;
            float var  = (tq - ts * ts / fm) / (fm - 1.f);
            mM[f] = mean;
            mR[f] = 1.f / (sqrtf(var) + EPSF);
        }
        __syncthreads();

        float4* dsto = ((float4*)out_opes) + (size_t)b * CHUNK;
#pragma unroll 4
        for (int i = threadIdx.x; i < CHUNK; i += PT) {
            float4 v = buf[i];
            int g = (i & 1) * 4;
            float4 o;
            o.x = (v.x - M[g + 0]) * R[g + 0];
            o.y = (v.y - M[g + 1]) * R[g + 1];
            o.z = (v.z - M[g + 2]) * R[g + 2];
            o.w = (v.w - M[g + 3]) * R[g + 3];
            __stcs(dsto + i, o);
        }
        if (threadIdx.x < NM * FM) {
            int f = threadIdx.x % FM;
            float x = ((const float*)smas4)[threadIdx.x];
            __stcs(out_mas + (size_t)b * NM * FM + threadIdx.x, (x - mM[f]) * mR[f]);
        }
        __syncthreads();   // all smem reads done before refill / reuse

        if (j + 1 < OPES_IT && threadIdx.x == 0) {
            const float4* nsrc = (const float4*)(opes + (size_t)(b + 1) * S * FO);
            mbar_expect_tx(mb0, SUBB); bulk_g2s(sbuf0, nsrc,       SUBB, mb0);
            mbar_expect_tx(mb1, SUBB); bulk_g2s(sbuf1, nsrc + SUB, SUBB, mb1);
        }
    }
}

extern "C" void kernel_launch(void* const* d_in, const int* in_sizes, int n_in,
                              void* d_out, int out_size) {
    const float* raw_opes = (const float*)d_in[0];
    const float* raw_mas  = (const float*)d_in[1];
    const float* proc     = (const float*)d_in[2];
    const int*   nums     = (const int*)d_in[3];

    float* out_opes = (float*)d_out;
    float* out_mas  = out_opes + (size_t)NB * S * FO;
    float* out_proc = out_mas  + (size_t)NB * NM * FM;

    cudaFuncSetAttribute(fused_k, cudaFuncAttributeMaxDynamicSharedMemorySize, CHUNK * 16);

    fused_k<<<GRID, PT, CHUNK * 16>>>((const float4*)proc, (float4*)out_proc,
                                      raw_opes, raw_mas, nums, out_opes, out_mas);
}

// round 6
// speedup vs baseline: 1.6987x; 1.6429x over previous
#include <cuda_runtime.h>
#include <math.h>

#define NB 256
#define S  4096
#define FO 8
#define NM 64
#define FM 6
#define EPSF 1e-5f

#define PBLK 16     // stats sub-blocks per proc instance (4096 float4 each)
#define NPB  32     // norm sub-blocks per proc instance (2048 float4 each)
#define OPB  8      // norm sub-blocks per opes instance (1024 float4 each)

// -------- device scratch (no allocations allowed) --------
__device__ float g_part[NB][PBLK][4];    // per-block proc partials (no atomics, no zeroing)
__device__ float g_omean[NB * FO];
__device__ float g_orstd[NB * FO];
__device__ float g_mmean[NB * FM];
__device__ float g_mrstd[NB * FM];

__device__ __forceinline__ float warp_sum(float v) {
#pragma unroll
    for (int o = 16; o > 0; o >>= 1) v += __shfl_down_sync(0xffffffffu, v, o);
    return v;
}

// ==================== Kernel A: all statistics, one launch ====================
// blocks [0, NB*PBLK)            : proc partial reduce (sum, sumsq, nnz)
// blocks [NB*PBLK, NB*PBLK+NB)   : opes (ragged masked) + mas stats
__global__ void __launch_bounds__(256)
statsA_k(const float4* __restrict__ pt,
         const float* __restrict__ opes, const float* __restrict__ mas,
         const int* __restrict__ nums) {
    const int bid = blockIdx.x;

    if (bid < NB * PBLK) {
        // ---------------- proc partial reduce ----------------
        const int b   = bid >> 4;
        const int sub = bid & (PBLK - 1);
        const float4* src = pt + (size_t)b * (S * NM / 4) + (size_t)sub * 4096;

        float s = 0.f, ss = 0.f, c = 0.f;
        // 4096 float4 per block; 4 front-batched LDG.128 per thread per step
        for (int i0 = threadIdx.x; i0 < 4096; i0 += 1024) {
            float4 v[4];
#pragma unroll
            for (int k = 0; k < 4; k++) v[k] = __ldcs(&src[i0 + k * 256]);
#pragma unroll
            for (int k = 0; k < 4; k++) {
                s  += (v[k].x + v[k].y) + (v[k].z + v[k].w);
                ss += (v[k].x * v[k].x + v[k].y * v[k].y) + (v[k].z * v[k].z + v[k].w * v[k].w);
                c  += (float)((v[k].x != 0.f) + (v[k].y != 0.f) + (v[k].z != 0.f) + (v[k].w != 0.f));
            }
        }

        __shared__ float sh[3][8];
        int lane = threadIdx.x & 31, w = threadIdx.x >> 5;
        s = warp_sum(s); ss = warp_sum(ss); c = warp_sum(c);
        if (lane == 0) { sh[0][w] = s; sh[1][w] = ss; sh[2][w] = c; }
        __syncthreads();
        if (threadIdx.x == 0) {
            float ts = 0.f, tss = 0.f, tc = 0.f;
#pragma unroll
            for (int i = 0; i < 8; i++) { ts += sh[0][i]; tss += sh[1][i]; tc += sh[2][i]; }
            g_part[b][sub][0] = ts;
            g_part[b][sub][1] = tss;
            g_part[b][sub][2] = tc;
        }
    } else {
        // ---------------- opes + mas stats (one block per instance) ----------------
        const int b = bid - NB * PBLK;
        const int n = nums[b];

        float s[FO], q[FO];
#pragma unroll
        for (int f = 0; f < FO; f++) { s[f] = 0.f; q[f] = 0.f; }

        const float4* op = (const float4*)(opes + (size_t)b * S * FO);
        for (int r = threadIdx.x; r < n; r += 256) {
            float4 a  = op[r * 2];
            float4 b4 = op[r * 2 + 1];
            float x[FO] = {a.x, a.y, a.z, a.w, b4.x, b4.y, b4.z, b4.w};
#pragma unroll
            for (int f = 0; f < FO; f++) { s[f] += x[f]; q[f] += x[f] * x[f]; }
        }

        __shared__ float sh[16][8];
        int lane = threadIdx.x & 31, w = threadIdx.x >> 5;
#pragma unroll
        for (int f = 0; f < FO; f++) {
            float rs = warp_sum(s[f]);
            float rq = warp_sum(q[f]);
            if (lane == 0) { sh[f][w] = rs; sh[f + 8][w] = rq; }
        }
        __syncthreads();

        if (threadIdx.x < FO) {
            int f = threadIdx.x;
            float ts = 0.f, tq = 0.f;
#pragma unroll
            for (int i = 0; i < 8; i++) { ts += sh[f][i]; tq += sh[f + 8][i]; }
            float fn  = (float)n;
            float m   = ts / fn;
            float var = (tq - ts * ts / fn) / (fn - 1.f);
            g_omean[b * FO + f] = m;
            g_orstd[b * FO + f] = 1.f / (sqrtf(var) + EPSF);
        }

        if (threadIdx.x >= 32 && threadIdx.x < 32 + FM) {
            int f = threadIdx.x - 32;
            const float* mp = mas + (size_t)b * NM * FM + f;
            float ts = 0.f, tq = 0.f;
#pragma unroll
            for (int m = 0; m < NM; m++) { float x = mp[m * FM]; ts += x; tq += x * x; }
            float fm   = (float)NM;
            float mean = ts / fm;
            float var  = (tq - ts * ts / fm) / (fm - 1.f);
            g_mmean[b * FM + f] = mean;
            g_mrstd[b * FM + f] = 1.f / (sqrtf(var) + EPSF);
        }
    }
}

// ==================== Kernel B: all normalization, one launch ====================
// blocks [0, NB*NPB)                      : proc normalize (2048 float4 each)
// blocks [NB*NPB, NB*NPB+NB*OPB)          : opes normalize (1024 float4 each)
// blocks [NB*NPB+NB*OPB, +384)            : mas normalize
__global__ void __launch_bounds__(256)
normB_k(const float4* __restrict__ pt, float4* __restrict__ out_proc,
        const float4* __restrict__ opes4, float4* __restrict__ out_opes,
        const float* __restrict__ mas, float* __restrict__ out_mas) {
    const int bid = blockIdx.x;

    if (bid < NB * NPB) {
        // ---------------- proc normalize ----------------
        const int b   = bid >> 5;
        const int sub = bid & (NPB - 1);

        __shared__ float sm, sr;
        if (threadIdx.x < 32) {
            int lane = threadIdx.x;
            float s = 0.f, ss = 0.f, c = 0.f;
            if (lane < PBLK) {
                s  = g_part[b][lane][0];
                ss = g_part[b][lane][1];
                c  = g_part[b][lane][2];
            }
#pragma unroll
            for (int o = 8; o > 0; o >>= 1) {
                s  += __shfl_down_sync(0xffffffffu, s, o);
                ss += __shfl_down_sync(0xffffffffu, ss, o);
                c  += __shfl_down_sync(0xffffffffu, c, o);
            }
            if (lane == 0) {
                float m   = s / c;
                float var = (ss - s * s / c) / (c - 1.f);
                sm = m;
                sr = 1.f / (sqrtf(var) + EPSF);
            }
        }
        __syncthreads();
        const float m = sm, r = sr;

        const size_t base = (size_t)b * (S * NM / 4) + (size_t)sub * 2048;
        const float4* src = pt + base;
        float4*       dst = out_proc + base;
        // 2048 float4 per block; 2 front-batched loads per step
        for (int i0 = threadIdx.x; i0 < 2048; i0 += 512) {
            float4 v0 = __ldcs(&src[i0]);
            float4 v1 = __ldcs(&src[i0 + 256]);
            float4 o0, o1;
            o0.x = (v0.x != 0.f) ? (v0.x - m) * r : 0.f;
            o0.y = (v0.y != 0.f) ? (v0.y - m) * r : 0.f;
            o0.z = (v0.z != 0.f) ? (v0.z - m) * r : 0.f;
            o0.w = (v0.w != 0.f) ? (v0.w - m) * r : 0.f;
            o1.x = (v1.x != 0.f) ? (v1.x - m) * r : 0.f;
            o1.y = (v1.y != 0.f) ? (v1.y - m) * r : 0.f;
            o1.z = (v1.z != 0.f) ? (v1.z - m) * r : 0.f;
            o1.w = (v1.w != 0.f) ? (v1.w - m) * r : 0.f;
            __stcs(&dst[i0], o0);
            __stcs(&dst[i0 + 256], o1);
        }
    } else if (bid < NB * NPB + NB * OPB) {
        // ---------------- opes normalize ----------------
        const int obid = bid - NB * NPB;
        const int b    = obid >> 3;
        const int base = b * 8192 + (obid & (OPB - 1)) * 1024;

        __shared__ float mm[FO], rr[FO];
        if (threadIdx.x < FO) {
            mm[threadIdx.x] = g_omean[b * FO + threadIdx.x];
            rr[threadIdx.x] = g_orstd[b * FO + threadIdx.x];
        }
        __syncthreads();

        for (int i0 = threadIdx.x; i0 < 1024; i0 += 512) {
            float4 v0 = __ldcs(&opes4[base + i0]);
            float4 v1 = __ldcs(&opes4[base + i0 + 256]);
            // float4-index parity selects feature half
            const float* M0 = &mm[(i0 & 1) * 4];
            const float* R0 = &rr[(i0 & 1) * 4];
            const float* M1 = &mm[((i0 + 256) & 1) * 4];
            const float* R1 = &rr[((i0 + 256) & 1) * 4];
            float4 o0, o1;
            o0.x = (v0.x - M0[0]) * R0[0];
            o0.y = (v0.y - M0[1]) * R0[1];
            o0.z = (v0.z - M0[2]) * R0[2];
            o0.w = (v0.w - M0[3]) * R0[3];
            o1.x = (v1.x - M1[0]) * R1[0];
            o1.y = (v1.y - M1[1]) * R1[1];
            o1.z = (v1.z - M1[2]) * R1[2];
            o1.w = (v1.w - M1[3]) * R1[3];
            __stcs(&out_opes[base + i0], o0);
            __stcs(&out_opes[base + i0 + 256], o1);
        }
    } else {
        // ---------------- mas normalize ----------------
        const int mbid = bid - NB * NPB - NB * OPB;
        const int i = mbid * 256 + threadIdx.x;
        const int N = NB * NM * FM;
        if (i < N) {
            int b = i / (NM * FM);
            int f = i % FM;
            out_mas[i] = (mas[i] - g_mmean[b * FM + f]) * g_mrstd[b * FM + f];
        }
    }
}

extern "C" void kernel_launch(void* const* d_in, const int* in_sizes, int n_in,
                              void* d_out, int out_size) {
    const float* raw_opes = (const float*)d_in[0];
    const float* raw_mas  = (const float*)d_in[1];
    const float* proc     = (const float*)d_in[2];
    const int*   nums     = (const int*)d_in[3];

    float* out_opes = (float*)d_out;
    float* out_mas  = out_opes + (size_t)NB * S * FO;
    float* out_proc = out_mas  + (size_t)NB * NM * FM;

    const int gridA = NB * PBLK + NB;                         // 4352
    const int gridB = NB * NPB + NB * OPB + (NB * NM * FM + 255) / 256;  // 8192+2048+384

    statsA_k<<<gridA, 256>>>((const float4*)proc, raw_opes, raw_mas, nums);
    normB_k<<<gridB, 256>>>((const float4*)proc, (float4*)out_proc,
                            (const float4*)raw_opes, (float4*)out_opes,
                            raw_mas, out_mas);
}